// round 4
// baseline (speedup 1.0000x reference)
#include <cuda_runtime.h>

#define N_TOTAL   100000
#define FEAT      128
#define NB_ROWS   50000
#define KNEI      16
#define EMB       128
#define RTILE     64
#define TPB       256
#define NBLK      ((NB_ROWS + RTILE - 1) / RTILE)   // 782
#define AGG_LD    132
#define SMEM_BYTES ((FEAT * EMB + RTILE * AGG_LD) * 4)   // 99328

typedef unsigned long long ull;

// Scratch (allocation-free rule: __device__ globals)
__device__ float g_psum[NBLK * EMB];
__device__ float g_psq [NBLK * EMB];
__device__ float g_scale[EMB];
__device__ float g_bias [EMB];
__device__ unsigned int g_arrival = 0;

// ---- packed f32x2 helpers (Blackwell) ----
__device__ __forceinline__ ull pack2(float x) {
    ull r;
    asm("mov.b64 %0, {%1, %1};" : "=l"(r) : "r"(__float_as_uint(x)));
    return r;
}
__device__ __forceinline__ void fma2(ull& d, ull a, ull b) {
    asm("fma.rn.f32x2 %0, %1, %2, %0;" : "+l"(d) : "l"(a), "l"(b));
}
__device__ __forceinline__ void unpack2(ull v, float& lo, float& hi) {
    unsigned int l, h;
    asm("mov.b64 {%0, %1}, %2;" : "=r"(l), "=r"(h) : "l"(v));
    lo = __uint_as_float(l);
    hi = __uint_as_float(h);
}

// ============================================================================
// Kernel A: gather-mean + GEMM (8x8 reg tile) + column partials + last-block
// BN-stats finalize.  97KB smem -> 2 CTAs/SM.
// ============================================================================
__global__ void __launch_bounds__(TPB, 2)
fused_a(const float* __restrict__ raw,
        const float* __restrict__ W,
        const int* __restrict__ nidx,
        const float* __restrict__ gamma,
        const float* __restrict__ beta,
        float* __restrict__ out)
{
    extern __shared__ float smem[];
    float* s_w   = smem;              // [128][128] weight, row k contiguous
    float* s_agg = smem + FEAT * EMB; // [64][AGG_LD]

    const int tid = threadIdx.x;
    const int bid = blockIdx.x;
    const int rowBase = bid * RTILE;

    // --- load weight to smem ---
    {
        const float4* Wv = (const float4*)W;
        float4* sv = (float4*)s_w;
        for (int i = tid; i < FEAT * EMB / 4; i += TPB) sv[i] = Wv[i];
    }

    // --- gather + mean: 8 warps x 8 rows; lane covers 4 cols (float4) ---
    {
        const int warp = tid >> 5, lane = tid & 31;
        #pragma unroll
        for (int i = 0; i < 8; i++) {
            const int rl = warp * 8 + i;
            const int rg = rowBase + rl;
            float4 acc = make_float4(0.f, 0.f, 0.f, 0.f);
            if (rg < NB_ROWS) {
                int my = 0;
                if (lane < KNEI) my = nidx[rg * KNEI + lane];
                #pragma unroll
                for (int k = 0; k < KNEI; k++) {
                    const int id = __shfl_sync(0xffffffffu, my, k);
                    const float4 v =
                        ((const float4*)(raw + (long long)id * FEAT))[lane];
                    acc.x += v.x; acc.y += v.y; acc.z += v.z; acc.w += v.w;
                }
                const float inv = 1.0f / KNEI;
                acc.x *= inv; acc.y *= inv; acc.z *= inv; acc.w *= inv;
            }
            ((float4*)(s_agg + rl * AGG_LD))[lane] = acc;
        }
    }
    __syncthreads();

    // --- GEMM: 128 threads. thread (ty,tx): rows {ty + 8i}, cols
    //     {tx*4..+3} and {64+tx*4..+3}.  8x8 outputs per thread. ---
    const int tx = tid & 15, ty = (tid >> 4) & 7;
    ull acc[8][4];
    #pragma unroll
    for (int i = 0; i < 8; i++)
        #pragma unroll
        for (int j = 0; j < 4; j++) acc[i][j] = 0ULL;

    if (tid < 128) {
        const float* aBase = s_agg + ty * AGG_LD;
        const float* bBase = s_w + tx * 4;

        for (int k0 = 0; k0 < FEAT; k0 += 4) {
            float4 a[8];
            #pragma unroll
            for (int i = 0; i < 8; i++)
                a[i] = *(const float4*)(aBase + (8 * i) * AGG_LD + k0);

            #pragma unroll
            for (int kk = 0; kk < 4; kk++) {
                const ulonglong2 b0 =
                    *(const ulonglong2*)(bBase + (k0 + kk) * EMB);
                const ulonglong2 b1 =
                    *(const ulonglong2*)(bBase + (k0 + kk) * EMB + 64);
                #pragma unroll
                for (int i = 0; i < 8; i++) {
                    const float as = (kk == 0) ? a[i].x : (kk == 1) ? a[i].y
                                   : (kk == 2) ? a[i].z : a[i].w;
                    const ull av = pack2(as);
                    fma2(acc[i][0], av, b0.x);
                    fma2(acc[i][1], av, b0.y);
                    fma2(acc[i][2], av, b1.x);
                    fma2(acc[i][3], av, b1.y);
                }
            }
        }

        // --- write pre-BN x (two 16B stores per row) ---
        #pragma unroll
        for (int i = 0; i < 8; i++) {
            const int rg = rowBase + ty + 8 * i;
            if (rg < NB_ROWS) {
                ulonglong2 v0; v0.x = acc[i][0]; v0.y = acc[i][1];
                ulonglong2 v1; v1.x = acc[i][2]; v1.y = acc[i][3];
                *(ulonglong2*)(out + (long long)rg * EMB + tx * 4)      = v0;
                *(ulonglong2*)(out + (long long)rg * EMB + 64 + tx * 4) = v1;
            }
        }
    }

    __syncthreads();   // all GEMM reads of s_agg complete before reuse

    // --- column sum / sumsq partials (invalid rows contributed exact 0) ---
    float* s_sum = s_agg;          // [8][128]
    float* s_sq  = s_agg + 1024;   // [8][128]
    if (tid < 128) {
        #pragma unroll
        for (int j = 0; j < 4; j++) {
            float s0 = 0.f, s1 = 0.f, q0 = 0.f, q1 = 0.f;
            #pragma unroll
            for (int i = 0; i < 8; i++) {
                float x0, x1;
                unpack2(acc[i][j], x0, x1);
                s0 += x0; q0 += x0 * x0;
                s1 += x1; q1 += x1 * x1;
            }
            const int c = (j < 2) ? (tx * 4 + 2 * j)
                                  : (64 + tx * 4 + 2 * (j - 2));
            s_sum[ty * 128 + c]     = s0;
            s_sum[ty * 128 + c + 1] = s1;
            s_sq [ty * 128 + c]     = q0;
            s_sq [ty * 128 + c + 1] = q1;
        }
    }
    __syncthreads();

    if (tid < 128) {
        float s = 0.f, q = 0.f;
        #pragma unroll
        for (int t = 0; t < 8; t++) {
            s += s_sum[t * 128 + tid];
            q += s_sq [t * 128 + tid];
        }
        g_psum[bid * 128 + tid] = s;
        g_psq [bid * 128 + tid] = q;
    }

    // --- last block finalizes BN scale/bias ---
    __threadfence();
    __shared__ unsigned int s_last;
    if (tid == 0)
        s_last = (atomicAdd(&g_arrival, 1u) == (unsigned)(NBLK - 1)) ? 1u : 0u;
    __syncthreads();
    if (s_last) {
        const int c = tid & 127, p = tid >> 7;     // 2-way split
        float s = 0.f, q = 0.f;
        for (int b = p; b < NBLK; b += 2) {
            s += g_psum[b * 128 + c];
            q += g_psq [b * 128 + c];
        }
        smem[p * 128 + c]       = s;
        smem[256 + p * 128 + c] = q;
        __syncthreads();
        if (tid < 128) {
            const float ss = smem[tid] + smem[128 + tid];
            const float qq = smem[256 + tid] + smem[384 + tid];
            const float invN = 1.0f / (float)NB_ROWS;
            const float mean = ss * invN;
            const float var  = qq * invN - mean * mean;
            const float sc   = gamma[tid] * rsqrtf(var + 1e-5f);
            g_scale[tid] = sc;
            g_bias [tid] = beta[tid] - mean * sc;
        }
        if (tid == 0) g_arrival = 0;   // reset for next graph replay
    }
}

// ============================================================================
// Kernel C: in-place BN apply + LeakyReLU (vectorized float4).
// ============================================================================
__global__ void __launch_bounds__(256)
bn_c(float* __restrict__ out)
{
    const int i = blockIdx.x * blockDim.x + threadIdx.x;       // float4 index
    if (i >= NB_ROWS * EMB / 4) return;
    float4 v = ((float4*)out)[i];
    const int c4 = i & 31;
    const float4 sc = ((const float4*)g_scale)[c4];
    const float4 bs = ((const float4*)g_bias)[c4];
    float x;
    x = v.x * sc.x + bs.x; v.x = (x >= 0.f) ? x : 0.01f * x;
    x = v.y * sc.y + bs.y; v.y = (x >= 0.f) ? x : 0.01f * x;
    x = v.z * sc.z + bs.z; v.z = (x >= 0.f) ? x : 0.01f * x;
    x = v.w * sc.w + bs.w; v.w = (x >= 0.f) ? x : 0.01f * x;
    ((float4*)out)[i] = v;
}

// ============================================================================
extern "C" void kernel_launch(void* const* d_in, const int* in_sizes, int n_in,
                              void* d_out, int out_size)
{
    const float* raw   = (const float*)d_in[0];
    const float* W     = (const float*)d_in[1];
    const float* gamma = (const float*)d_in[2];
    const float* beta  = (const float*)d_in[3];
    const int*   nidx  = (const int*)d_in[4];
    float* out = (float*)d_out;

    cudaFuncSetAttribute(fused_a, cudaFuncAttributeMaxDynamicSharedMemorySize,
                         SMEM_BYTES);

    fused_a<<<NBLK, TPB, SMEM_BYTES>>>(raw, W, nidx, gamma, beta, out);
    const int n4 = NB_ROWS * EMB / 4;
    bn_c<<<(n4 + 255) / 256, 256>>>(out);
}

// round 5
// speedup vs baseline: 1.1292x; 1.1292x over previous
#include <cuda_runtime.h>

#define N_TOTAL   100000
#define FEAT      128
#define NB_ROWS   50000
#define KNEI      16
#define EMB       128
#define RTILE     64
#define TPB       256
#define NBLK      ((NB_ROWS + RTILE - 1) / RTILE)   // 782
#define GRID      296                                // 2 CTAs x 148 SMs (<=152)
#define AGG_LD    132
#define SMEM_BYTES ((FEAT * EMB + RTILE * AGG_LD) * 4)   // 99328

typedef unsigned long long ull;

// Scratch (allocation-free rule: __device__ globals)
__device__ float g_psum[GRID * EMB];
__device__ float g_psq [GRID * EMB];
__device__ float g_scale[EMB];
__device__ float g_bias [EMB];
__device__ unsigned int g_arrival = 0;
__device__ unsigned int g_done    = 0;
__device__ unsigned int g_ready   = 0;

// ---- packed f32x2 helpers (Blackwell) ----
__device__ __forceinline__ ull pack2(float x) {
    ull r;
    asm("mov.b64 %0, {%1, %1};" : "=l"(r) : "r"(__float_as_uint(x)));
    return r;
}
__device__ __forceinline__ void fma2(ull& d, ull a, ull b) {
    asm("fma.rn.f32x2 %0, %1, %2, %0;" : "+l"(d) : "l"(a), "l"(b));
}
__device__ __forceinline__ void unpack2(ull v, float& lo, float& hi) {
    unsigned int l, h;
    asm("mov.b64 {%0, %1}, %2;" : "=r"(l), "=r"(h) : "l"(v));
    lo = __uint_as_float(l);
    hi = __uint_as_float(h);
}

// ============================================================================
// Persistent kernel: gather-mean + GEMM over ~2.6 tiles/CTA, in-register
// cross-tile stats, grid barrier, last-CTA finalize, per-CTA BN apply.
// ============================================================================
__global__ void __launch_bounds__(TPB, 2)
fused_persist(const float* __restrict__ raw,
              const float* __restrict__ W,
              const int* __restrict__ nidx,
              const float* __restrict__ gamma,
              const float* __restrict__ beta,
              float* __restrict__ out)
{
    extern __shared__ float smem[];
    float* s_w   = smem;              // [128][128] weight, row k contiguous
    float* s_agg = smem + FEAT * EMB; // [64][AGG_LD]

    const int tid  = threadIdx.x;
    const int bid  = blockIdx.x;
    const int warp = tid >> 5, lane = tid & 31;
    const int tx = tid & 15, ty = tid >> 4;

    // --- load weight to smem once per CTA ---
    {
        const float4* Wv = (const float4*)W;
        float4* sv = (float4*)s_w;
        for (int i = tid; i < FEAT * EMB / 4; i += TPB) sv[i] = Wv[i];
    }

    // Cross-tile per-thread column accumulators (8 columns each).
    float cs[8], cq[8];
    #pragma unroll
    for (int k = 0; k < 8; k++) { cs[k] = 0.f; cq[k] = 0.f; }

    // =========================== compute phase ===========================
    for (int t = bid; t < NBLK; t += GRID) {
        const int rowBase = t * RTILE;
        __syncthreads();   // s_agg safe to overwrite (covers W-load on iter 0)

        // --- gather + mean: 8 warps x 8 rows; lane covers float4 cols ---
        #pragma unroll
        for (int i = 0; i < 8; i++) {
            const int rl = warp * 8 + i;
            const int rg = rowBase + rl;
            float4 a4 = make_float4(0.f, 0.f, 0.f, 0.f);
            if (rg < NB_ROWS) {
                int my = 0;
                if (lane < KNEI) my = nidx[rg * KNEI + lane];
                #pragma unroll
                for (int k = 0; k < KNEI; k++) {
                    const int id = __shfl_sync(0xffffffffu, my, k);
                    const float4 v =
                        ((const float4*)(raw + (long long)id * FEAT))[lane];
                    a4.x += v.x; a4.y += v.y; a4.z += v.z; a4.w += v.w;
                }
                const float inv = 1.0f / KNEI;
                a4.x *= inv; a4.y *= inv; a4.z *= inv; a4.w *= inv;
            }
            ((float4*)(s_agg + rl * AGG_LD))[lane] = a4;
        }
        __syncthreads();

        // --- GEMM: thread (ty,tx): rows ty*4..+3, cols tx*4..+3 & 64+tx*4..+3
        ull acc[4][4];
        #pragma unroll
        for (int i = 0; i < 4; i++)
            #pragma unroll
            for (int j = 0; j < 4; j++) acc[i][j] = 0ULL;

        const float* aBase = s_agg + (ty * 4) * AGG_LD;
        const float* bBase = s_w + tx * 4;

        #pragma unroll 2
        for (int k0 = 0; k0 < FEAT; k0 += 4) {
            float4 a[4];
            #pragma unroll
            for (int i = 0; i < 4; i++)
                a[i] = *(const float4*)(aBase + i * AGG_LD + k0);

            #pragma unroll
            for (int kk = 0; kk < 4; kk++) {
                const ulonglong2 b0 =
                    *(const ulonglong2*)(bBase + (k0 + kk) * EMB);
                const ulonglong2 b1 =
                    *(const ulonglong2*)(bBase + (k0 + kk) * EMB + 64);
                #pragma unroll
                for (int i = 0; i < 4; i++) {
                    const float as = (kk == 0) ? a[i].x : (kk == 1) ? a[i].y
                                   : (kk == 2) ? a[i].z : a[i].w;
                    const ull av = pack2(as);
                    fma2(acc[i][0], av, b0.x);
                    fma2(acc[i][1], av, b0.y);
                    fma2(acc[i][2], av, b1.x);
                    fma2(acc[i][3], av, b1.y);
                }
            }
        }

        // --- write pre-BN x + accumulate column stats in registers ---
        #pragma unroll
        for (int i = 0; i < 4; i++) {
            const int rg = rowBase + ty * 4 + i;
            if (rg < NB_ROWS) {
                ulonglong2 v0; v0.x = acc[i][0]; v0.y = acc[i][1];
                ulonglong2 v1; v1.x = acc[i][2]; v1.y = acc[i][3];
                *(ulonglong2*)(out + (long long)rg * EMB + tx * 4)      = v0;
                *(ulonglong2*)(out + (long long)rg * EMB + 64 + tx * 4) = v1;
            }
            // invalid rows hold exact 0 accumulators -> contribute nothing
            #pragma unroll
            for (int j = 0; j < 4; j++) {
                float x0, x1;
                unpack2(acc[i][j], x0, x1);
                cs[2 * j]     += x0;  cq[2 * j]     += x0 * x0;
                cs[2 * j + 1] += x1;  cq[2 * j + 1] += x1 * x1;
            }
        }
    }

    // ====================== block-level stats reduce ======================
    __syncthreads();   // all GEMM reads of s_agg finished
    float* s_sum = s_agg;          // [16][128]
    float* s_sq  = s_agg + 2048;   // [16][128]
    #pragma unroll
    for (int k = 0; k < 8; k++) {
        const int j = k >> 1;
        const int c = ((j < 2) ? (tx * 4 + 2 * j)
                               : (64 + tx * 4 + 2 * (j - 2))) + (k & 1);
        s_sum[ty * 128 + c] = cs[k];
        s_sq [ty * 128 + c] = cq[k];
    }
    __syncthreads();
    if (tid < 128) {
        float s = 0.f, q = 0.f;
        #pragma unroll
        for (int t8 = 0; t8 < 16; t8++) {
            s += s_sum[t8 * 128 + tid];
            q += s_sq [t8 * 128 + tid];
        }
        g_psum[bid * 128 + tid] = s;
        g_psq [bid * 128 + tid] = q;
    }

    // ========================== grid barrier ==========================
    __threadfence();
    __shared__ unsigned int s_last;
    if (tid == 0)
        s_last = (atomicAdd(&g_arrival, 1u) == (unsigned)(GRID - 1)) ? 1u : 0u;
    __syncthreads();

    if (s_last) {
        // last CTA: reduce GRID partials (fixed order -> deterministic)
        const int c = tid & 127, p = tid >> 7;     // 2-way split
        float s = 0.f, q = 0.f;
        for (int b = p; b < GRID; b += 2) {
            s += g_psum[b * 128 + c];
            q += g_psq [b * 128 + c];
        }
        s_sum[p * 128 + c] = s;
        s_sq [p * 128 + c] = q;
        __syncthreads();
        if (tid < 128) {
            const float ss = s_sum[tid] + s_sum[128 + tid];
            const float qq = s_sq [tid] + s_sq [128 + tid];
            const float invN = 1.0f / (float)NB_ROWS;
            const float mean = ss * invN;
            const float var  = qq * invN - mean * mean;
            const float sc   = gamma[tid] * rsqrtf(var + 1e-5f);
            g_scale[tid] = sc;
            g_bias [tid] = beta[tid] - mean * sc;
        }
        __syncthreads();
        __threadfence();
        if (tid == 0) atomicExch(&g_ready, 1u);
    } else {
        if (tid == 0) {
            unsigned int r;
            do {
                asm volatile("ld.acquire.gpu.b32 %0, [%1];"
                             : "=r"(r) : "l"(&g_ready));
                if (!r) __nanosleep(64);
            } while (!r);
        }
        __syncthreads();
    }

    // ================== BN apply + LeakyReLU on own tiles ==================
    if (tid < 128) {
        s_w[tid]       = g_scale[tid];
        s_w[128 + tid] = g_bias[tid];
    }
    __syncthreads();

    for (int t = bid; t < NBLK; t += GRID) {
        const int rowBase = t * RTILE;
        float4* o4 = (float4*)(out + (long long)rowBase * EMB);
        #pragma unroll
        for (int j = 0; j < 8; j++) {
            const int i = tid + j * TPB;           // 0..2047 float4s
            const int row = i >> 5;
            if (rowBase + row < NB_ROWS) {
                const int c4 = i & 31;
                float4 v = o4[i];
                const float4 sc = ((const float4*)s_w)[c4];
                const float4 bs = ((const float4*)(s_w + 128))[c4];
                float x;
                x = v.x * sc.x + bs.x; v.x = (x >= 0.f) ? x : 0.01f * x;
                x = v.y * sc.y + bs.y; v.y = (x >= 0.f) ? x : 0.01f * x;
                x = v.z * sc.z + bs.z; v.z = (x >= 0.f) ? x : 0.01f * x;
                x = v.w * sc.w + bs.w; v.w = (x >= 0.f) ? x : 0.01f * x;
                o4[i] = v;
            }
        }
    }

    // ---- exit barrier: last CTA to finish resets counters for replay ----
    __threadfence();
    __syncthreads();
    if (tid == 0) {
        if (atomicAdd(&g_done, 1u) == (unsigned)(GRID - 1)) {
            g_arrival = 0;
            g_done    = 0;
            g_ready   = 0;
            __threadfence();
        }
    }
}

// ============================================================================
extern "C" void kernel_launch(void* const* d_in, const int* in_sizes, int n_in,
                              void* d_out, int out_size)
{
    const float* raw   = (const float*)d_in[0];
    const float* W     = (const float*)d_in[1];
    const float* gamma = (const float*)d_in[2];
    const float* beta  = (const float*)d_in[3];
    const int*   nidx  = (const int*)d_in[4];
    float* out = (float*)d_out;

    cudaFuncSetAttribute(fused_persist,
                         cudaFuncAttributeMaxDynamicSharedMemorySize,
                         SMEM_BYTES);

    fused_persist<<<GRID, TPB, SMEM_BYTES>>>(raw, W, nidx, gamma, beta, out);
}